// round 13
// baseline (speedup 1.0000x reference)
#include <cuda_runtime.h>
#include <cuda_bf16.h>
#include <cstdint>

#define N_NODES 20000
#define N_EDGES 200000
#define FEAT    128
#define NB      8
#define SI      16
#define SO      16
#define NREL    230
#define WROW    (NB*SI*SO)       // 2048 floats per relation
#define NSUB    32               // sub-counters per relation
#define NCNT    (NREL*NSUB)      // 7360
#define EPW     32               // edges per warp (200000/32 = 6250 exact)
#define NWARPS  (N_EDGES/EPW)    // 6250
#define EDGE_CTAS ((NWARPS + 7) / 8)            // 782
#define MT 64
#define KT 32
#define GEMM_CTAS ((N_NODES + MT - 1) / MT)     // 313
#define DEPTH   8                // cp.async pipeline stages

// ---------------- packed f32x2 helpers -----------------------------------------
#define PACK_F32X2(out, lo, hi) \
    asm("mov.b64 %0, {%1, %2};" : "=l"(out) : "f"(lo), "f"(hi))
#define UNPACK_F32X2(lo, hi, in) \
    asm("mov.b64 {%0, %1}, %2;" : "=f"(lo), "=f"(hi) : "l"(in))
#define FMA_F32X2(d, a, b, c) \
    asm("fma.rn.f32x2 %0, %1, %2, %3;" : "=l"(d) : "l"(a), "l"(b), "l"(c))

// ---------------- cp.async helpers ----------------------------------------------
#define CP_ASYNC16(saddr, gptr) \
    asm volatile("cp.async.ca.shared.global [%0], [%1], 16;" \
                 :: "r"(saddr), "l"(gptr) : "memory")
#define CP_COMMIT() asm volatile("cp.async.commit_group;" ::: "memory")
#define CP_WAIT0()  asm volatile("cp.async.wait_group 0;" ::: "memory")
#define CP_WAIT7()  asm volatile("cp.async.wait_group 7;" ::: "memory")

__device__ __forceinline__ uint32_t s2u(const void* p) {
    return (uint32_t)__cvta_generic_to_shared(p);
}

// ---------------- scratch (device globals) -------------------------------------
__device__ float g_agg[(size_t)N_NODES * FEAT];      // 10.24 MB
__device__ float g_loop[(size_t)N_NODES * FEAT];     // 10.24 MB self-loop msg
__device__ int   g_counts[NCNT];                     // zero at load; re-zeroed by scan
__device__ int   g_cursor[NCNT];
__device__ int   g_rank[N_EDGES];                    // intra-bucket rank per edge
__device__ int4  g_edge[N_EDGES];                    // sorted {src,dst,type,norm}

// ---------------- K0: zero agg + histogram-with-rank ---------------------------
__global__ void zero_hist_kernel(const int* __restrict__ etype) {
    int i = blockIdx.x * blockDim.x + threadIdx.x;
    const int n4 = N_NODES * FEAT / 4;   // 640000
    if (i < n4) reinterpret_cast<float4*>(g_agg)[i] =
        make_float4(0.f, 0.f, 0.f, 0.f);
    if (i < N_EDGES) {
        int t = etype[i];
        int r = atomicAdd(&g_counts[t * NSUB + (i & (NSUB - 1))], 1);
        g_rank[i] = r;
    }
}

// ---------------- K1: exclusive scan over 7360 counters + reset ----------------
__global__ void __launch_bounds__(1024) scan_kernel() {
    __shared__ int sp[1024];
    int t = threadIdx.x;
    int base = t * 8;
    int v[8];
    int sum = 0;
    #pragma unroll
    for (int i = 0; i < 8; ++i) {
        if (base + i < NCNT) {
            v[i] = g_counts[base + i];
            g_counts[base + i] = 0;          // reset for next graph replay
        } else v[i] = 0;
        sum += v[i];
    }
    sp[t] = sum;
    __syncthreads();
    #pragma unroll
    for (int off = 1; off < 1024; off <<= 1) {
        int x = (t >= off) ? sp[t - off] : 0;
        __syncthreads();
        sp[t] += x;
        __syncthreads();
    }
    int run = sp[t] - sum;
    #pragma unroll
    for (int i = 0; i < 8; ++i) {
        if (base + i < NCNT) g_cursor[base + i] = run;
        run += v[i];
    }
}

// ---------------- K2: atomic-free scatter ----------------------------------------
__global__ void scatter_kernel(const int* __restrict__ etype,
                               const int* __restrict__ esrc,
                               const int* __restrict__ edst,
                               const float* __restrict__ enorm) {
    int e = blockIdx.x * blockDim.x + threadIdx.x;
    if (e < N_EDGES) {
        int t = etype[e];
        int c = t * NSUB + (e & (NSUB - 1));
        int pos = __ldg(&g_cursor[c]) + g_rank[e];
        g_edge[pos] = make_int4(esrc[e], edst[e], t, __float_as_int(enorm[e]));
    }
}

// ---------------- K3: fused edge-message (8-deep cp.async pipeline) + GEMM ------
__global__ void __launch_bounds__(256) fused_kernel(
    const float* __restrict__ h,
    const float* __restrict__ weight,
    const float* __restrict__ loop_weight)
{
    __shared__ __align__(16) union SMem {
        struct { float W[KT][FEAT]; float H[MT][KT + 4]; } g;       // 25.6 KB
        struct { int4 rec[8][32]; float4 hbuf[8][DEPTH][32]; } e;   // 36 KB
    } sm;

    if (blockIdx.x < EDGE_CTAS) {
        // ======================= EDGE BRANCH ====================================
        const int w    = threadIdx.x >> 5;
        const int warp = blockIdx.x * 8 + w;
        if (warp >= NWARPS) return;
        const int lane = threadIdx.x & 31;
        const int e0   = warp * EPW;
        const int b    = lane >> 2;
        const int q    = lane & 3;

        int4* srec = sm.e.rec[w];

        // stage all 32 edge records for this warp (one 16B cp.async per lane)
        CP_ASYNC16(s2u(&srec[lane]), &g_edge[e0 + lane]);
        CP_COMMIT();
        CP_WAIT0();
        __syncwarp();

        // prime DEPTH h-row stages (each lane copies its 16B slice of the row)
        #pragma unroll
        for (int s = 0; s < DEPTH; ++s) {
            int src = srec[s].x;                     // LDS broadcast
            CP_ASYNC16(s2u(&sm.e.hbuf[w][s][lane]),
                       h + (size_t)src * FEAT + lane * 4);
            CP_COMMIT();
        }

        unsigned long long w01[16], w23[16];
        int cur = -1;

        #pragma unroll 1
        for (int i = 0; i < EPW; ++i) {
            CP_WAIT7();                  // stage i complete (groups retire in order)
            __syncwarp();                // its smem writes visible warp-wide

            int4 rec = srec[i];          // LDS.128 broadcast

            if (rec.z != cur) {
                cur = rec.z;
                const char* wbase = reinterpret_cast<const char*>(
                    weight + (size_t)cur * WROW + b * (SI * SO) + q * 4);
                #pragma unroll
                for (int k = 0; k < 16; ++k) {
                    ulonglong2 wv = __ldg(reinterpret_cast<const ulonglong2*>(
                        wbase + k * (SO * 4)));
                    w01[k] = wv.x;
                    w23[k] = wv.y;
                }
            }

            const float4* hb = sm.e.hbuf[w][i & (DEPTH - 1)];
            float4 x0 = hb[b * 4 + 0];
            float4 x1 = hb[b * 4 + 1];
            float4 x2 = hb[b * 4 + 2];
            float4 x3 = hb[b * 4 + 3];

            unsigned long long a01 = 0ULL, a23 = 0ULL;
            #define EK(k, val) { unsigned long long _p;              \
                PACK_F32X2(_p, val, val);                             \
                FMA_F32X2(a01, _p, w01[k], a01);                      \
                FMA_F32X2(a23, _p, w23[k], a23); }
            EK(0,x0.x) EK(1,x0.y) EK(2,x0.z) EK(3,x0.w)
            EK(4,x1.x) EK(5,x1.y) EK(6,x1.z) EK(7,x1.w)
            EK(8,x2.x) EK(9,x2.y) EK(10,x2.z) EK(11,x2.w)
            EK(12,x3.x) EK(13,x3.y) EK(14,x3.z) EK(15,x3.w)
            #undef EK

            float en = __int_as_float(rec.w);
            float r0, r1, r2, r3;
            UNPACK_F32X2(r0, r1, a01);
            UNPACK_F32X2(r2, r3, a23);
            r0 *= en; r1 *= en; r2 *= en; r3 *= en;
            float* dst = g_agg + (size_t)rec.y * FEAT + lane * 4;
            asm volatile("red.global.add.v4.f32 [%0], {%1, %2, %3, %4};"
                         :: "l"(dst), "f"(r0), "f"(r1), "f"(r2), "f"(r3)
                         : "memory");

            __syncwarp();                // all lanes consumed stage i's buffer
            if (i + DEPTH < EPW) {
                int nsrc = srec[i + DEPTH].x;
                CP_ASYNC16(s2u(&sm.e.hbuf[w][(i + DEPTH) & (DEPTH - 1)][lane]),
                           h + (size_t)nsrc * FEAT + lane * 4);
            }
            CP_COMMIT();                 // one group per iter keeps ordering
        }
    } else {
        // ======================= GEMM BRANCH: g_loop = h @ loop_weight ==========
        const int tid = threadIdx.x;
        const int tm  = tid >> 5;
        const int to  = tid & 31;
        const int n0  = (blockIdx.x - EDGE_CTAS) * MT;

        unsigned long long acc01[8], acc23[8];
        #pragma unroll
        for (int r = 0; r < 8; ++r) { acc01[r] = 0ULL; acc23[r] = 0ULL; }

        for (int kt = 0; kt < FEAT / KT; ++kt) {
            #pragma unroll
            for (int j = 0; j < 4; ++j) {
                int idx = tid + j * 256;
                int r   = idx >> 5;
                int c4  = idx & 31;
                float4 v = __ldg(reinterpret_cast<const float4*>(
                    loop_weight + (size_t)(kt * KT + r) * FEAT + c4 * 4));
                *reinterpret_cast<float4*>(&sm.g.W[r][c4 * 4]) = v;
            }
            #pragma unroll
            for (int j = 0; j < 2; ++j) {
                int idx = tid + j * 256;
                int r   = idx >> 3;
                int c4  = idx & 7;
                int n   = n0 + r;
                float4 v = make_float4(0.f, 0.f, 0.f, 0.f);
                if (n < N_NODES)
                    v = __ldg(reinterpret_cast<const float4*>(
                            h + (size_t)n * FEAT + kt * KT + c4 * 4));
                *reinterpret_cast<float4*>(&sm.g.H[r][c4 * 4]) = v;
            }
            __syncthreads();

            #pragma unroll
            for (int k = 0; k < KT; k += 4) {
                ulonglong2 wv0 = *reinterpret_cast<const ulonglong2*>(&sm.g.W[k + 0][to * 4]);
                ulonglong2 wv1 = *reinterpret_cast<const ulonglong2*>(&sm.g.W[k + 1][to * 4]);
                ulonglong2 wv2 = *reinterpret_cast<const ulonglong2*>(&sm.g.W[k + 2][to * 4]);
                ulonglong2 wv3 = *reinterpret_cast<const ulonglong2*>(&sm.g.W[k + 3][to * 4]);
                #pragma unroll
                for (int r = 0; r < 8; ++r) {
                    float4 hv = *reinterpret_cast<const float4*>(&sm.g.H[tm * 8 + r][k]);
                    unsigned long long h2;
                    PACK_F32X2(h2, hv.x, hv.x);
                    FMA_F32X2(acc01[r], h2, wv0.x, acc01[r]);
                    FMA_F32X2(acc23[r], h2, wv0.y, acc23[r]);
                    PACK_F32X2(h2, hv.y, hv.y);
                    FMA_F32X2(acc01[r], h2, wv1.x, acc01[r]);
                    FMA_F32X2(acc23[r], h2, wv1.y, acc23[r]);
                    PACK_F32X2(h2, hv.z, hv.z);
                    FMA_F32X2(acc01[r], h2, wv2.x, acc01[r]);
                    FMA_F32X2(acc23[r], h2, wv2.y, acc23[r]);
                    PACK_F32X2(h2, hv.w, hv.w);
                    FMA_F32X2(acc01[r], h2, wv3.x, acc01[r]);
                    FMA_F32X2(acc23[r], h2, wv3.y, acc23[r]);
                }
            }
            __syncthreads();
        }

        const int o0 = to * 4;
        #pragma unroll
        for (int r = 0; r < 8; ++r) {
            int n = n0 + tm * 8 + r;
            if (n < N_NODES) {
                float a0, a1, a2, a3;
                UNPACK_F32X2(a0, a1, acc01[r]);
                UNPACK_F32X2(a2, a3, acc23[r]);
                *reinterpret_cast<float4*>(g_loop + (size_t)n * FEAT + o0) =
                    make_float4(a0, a1, a2, a3);
            }
        }
    }
}

// ---------------- K4: epilogue + time-embedding ----------------------------------
__global__ void __launch_bounds__(256) epilogue_kernel(
    const float* __restrict__ node_norm,
    const float* __restrict__ h_bias,
    const float* __restrict__ time_embed,
    const int*   __restrict__ time_idx,
    float*       __restrict__ out)
{
    int idx = blockIdx.x * blockDim.x + threadIdx.x;
    const int total = N_NODES * (FEAT / 4);     // 640000
    if (idx >= total) return;
    int n  = idx >> 5;
    int c4 = idx & 31;
    int o0 = c4 * 4;

    float nn  = __ldg(&node_norm[n]);
    float4 hb = __ldg(reinterpret_cast<const float4*>(h_bias + o0));
    float4 ag = *reinterpret_cast<const float4*>(&g_agg [(size_t)n * FEAT + o0]);
    float4 lp = *reinterpret_cast<const float4*>(&g_loop[(size_t)n * FEAT + o0]);

    float4 res;
    res.x = fmaxf(ag.x * nn + hb.x + lp.x, 0.f);
    res.y = fmaxf(ag.y * nn + hb.y + lp.y, 0.f);
    res.z = fmaxf(ag.z * nn + hb.z + lp.z, 0.f);
    res.w = fmaxf(ag.w * nn + hb.w + lp.w, 0.f);
    *reinterpret_cast<float4*>(out + (size_t)n * FEAT + o0) = res;

    int ti = __ldg(&time_idx[n]);
    float4 te = __ldg(reinterpret_cast<const float4*>(
        time_embed + (size_t)ti * FEAT + o0));
    *reinterpret_cast<float4*>(out + (size_t)(N_NODES + n) * FEAT + o0) = te;
}

// ---------------- launch ---------------------------------------------------------
extern "C" void kernel_launch(void* const* d_in, const int* in_sizes, int n_in,
                              void* d_out, int out_size) {
    const float* h           = (const float*)d_in[0];
    const float* edge_norm   = (const float*)d_in[1];
    const float* node_norm   = (const float*)d_in[2];
    const float* weight      = (const float*)d_in[3];
    const float* h_bias      = (const float*)d_in[4];
    const float* loop_weight = (const float*)d_in[5];
    const float* time_embed  = (const float*)d_in[6];
    const int*   edge_src    = (const int*)d_in[7];
    const int*   edge_dst    = (const int*)d_in[8];
    const int*   edge_type   = (const int*)d_in[9];
    const int*   time_idx    = (const int*)d_in[10];
    float* out = (float*)d_out;

    {
        int n4 = N_NODES * FEAT / 4;
        zero_hist_kernel<<<(n4 + 255) / 256, 256>>>(edge_type);
    }
    scan_kernel<<<1, 1024>>>();
    scatter_kernel<<<(N_EDGES + 255) / 256, 256>>>(edge_type, edge_src,
                                                   edge_dst, edge_norm);
    fused_kernel<<<EDGE_CTAS + GEMM_CTAS, 256>>>(h, weight, loop_weight);
    {
        int total = N_NODES * (FEAT / 4);
        epilogue_kernel<<<(total + 255) / 256, 256>>>(
            node_norm, h_bias, time_embed, time_idx, out);
    }
}